// round 6
// baseline (speedup 1.0000x reference)
#include <cuda_runtime.h>
#include <math.h>

// Problem constants
#define B_  4
#define T_  4096
#define C_  1024
#define H_  16
#define D_  64
#define CS_ 64
#define NC_ 64
#define M_  (B_ * T_)      // 16384
#define F_  (3 * C_)       // 3072

// Scratch: qkv [B,T,3C] = 192MB, y [B,T,C] = 64MB (device globals — no allocs)
__device__ float g_qkv[50331648];   // 4*4096*3072
__device__ float g_y[16777216];     // 4*4096*1024

// ---------------------------------------------------------------------------
// TN GEMM: A [M,K] row-major, B [N,K] row-major, C[m,n] = sum_k A[m,k]*B[n,k]
// 128x128 block tile, BK=16, 256 threads, 8x8 register microtile.
// M,N,K all multiples of tile sizes for this problem (no bounds checks).
// ---------------------------------------------------------------------------
__global__ void __launch_bounds__(256) gemm_tn(const float* __restrict__ A,
                                               const float* __restrict__ B,
                                               float* __restrict__ C,
                                               int M, int N, int K)
{
    __shared__ float As[16][128];
    __shared__ float Bs[16][128];

    const int tid  = threadIdx.x;
    const int row0 = blockIdx.y * 128;
    const int col0 = blockIdx.x * 128;
    const int ty   = tid >> 4;   // 0..15
    const int tx   = tid & 15;   // 0..15

    float acc[8][8];
#pragma unroll
    for (int i = 0; i < 8; i++)
#pragma unroll
        for (int j = 0; j < 8; j++) acc[i][j] = 0.0f;

    for (int k0 = 0; k0 < K; k0 += 16) {
        // Load 128x16 tiles of A and B (transposed into smem)
#pragma unroll
        for (int it = 0; it < 2; it++) {
            int idx = tid + it * 256;          // 0..511
            int r   = idx >> 2;                // 0..127
            int c4  = (idx & 3) << 2;          // 0,4,8,12
            float4 a = *(const float4*)(A + (size_t)(row0 + r) * K + k0 + c4);
            As[c4 + 0][r] = a.x; As[c4 + 1][r] = a.y;
            As[c4 + 2][r] = a.z; As[c4 + 3][r] = a.w;
            float4 b = *(const float4*)(B + (size_t)(col0 + r) * K + k0 + c4);
            Bs[c4 + 0][r] = b.x; Bs[c4 + 1][r] = b.y;
            Bs[c4 + 2][r] = b.z; Bs[c4 + 3][r] = b.w;
        }
        __syncthreads();

#pragma unroll
        for (int kk = 0; kk < 16; kk++) {
            float af[8], bf[8];
#pragma unroll
            for (int i = 0; i < 8; i++) af[i] = As[kk][ty * 8 + i];
#pragma unroll
            for (int j = 0; j < 8; j++) bf[j] = Bs[kk][tx * 8 + j];
#pragma unroll
            for (int i = 0; i < 8; i++)
#pragma unroll
                for (int j = 0; j < 8; j++)
                    acc[i][j] += af[i] * bf[j];
        }
        __syncthreads();
    }

#pragma unroll
    for (int i = 0; i < 8; i++) {
        float4* cp = (float4*)(C + (size_t)(row0 + ty * 8 + i) * N + col0 + tx * 8);
        cp[0] = make_float4(acc[i][0], acc[i][1], acc[i][2], acc[i][3]);
        cp[1] = make_float4(acc[i][4], acc[i][5], acc[i][6], acc[i][7]);
    }
}

// ---------------------------------------------------------------------------
// Fused chunked attention: one block per (b, chunk, head).
// Loads q,k (RoPE applied on the fly), v into smem; 64x64 scores; softmax;
// p@v; writes y tile. All tiles [64][65] padded (65-float stride).
// ---------------------------------------------------------------------------
__global__ void __launch_bounds__(256) attn_kernel(const float* __restrict__ qkv,
                                                   float* __restrict__ y)
{
    extern __shared__ float sm[];
    float* qs = sm;                 // [64][65]
    float* ks = sm + 64 * 65;
    float* vs = sm + 2 * 64 * 65;
    float* ps = sm + 3 * 64 * 65;

    const int tid = threadIdx.x;
    const int blk = blockIdx.x;
    const int b = blk >> 10;          // NC_*H_ = 1024
    const int n = (blk >> 4) & 63;
    const int h = blk & 15;

    // ---- load q,k with RoPE; position within chunk = row r ----
    const float neg_ln_base_over_half = -9.210340371976184f / 32.0f; // -ln(10000)/32
    for (int idx = tid; idx < 64 * 32; idx += 256) {
        int r = idx >> 5;       // 0..63
        int j = idx & 31;       // 0..31
        const float* rowp = qkv + ((size_t)(b * T_ + n * 64 + r)) * 3072 + h * 64;
        float q1 = rowp[j],        q2 = rowp[j + 32];
        float k1 = rowp[1024 + j], k2 = rowp[1024 + j + 32];
        float invf = expf((float)j * neg_ln_base_over_half);   // 10000^(-j/32)
        float ang  = (float)r * invf;
        float cv, sv;
        sincosf(ang, &sv, &cv);   // sv = sin, cv = cos
        qs[r * 65 + j]      =  q1 * cv + q2 * sv;
        qs[r * 65 + j + 32] = -q1 * sv + q2 * cv;
        ks[r * 65 + j]      =  k1 * cv + k2 * sv;
        ks[r * 65 + j + 32] = -k1 * sv + k2 * cv;
    }
    // ---- load v ----
    for (int idx = tid; idx < 64 * 64; idx += 256) {
        int r  = idx >> 6;
        int dd = idx & 63;
        vs[r * 65 + dd] =
            qkv[((size_t)(b * T_ + n * 64 + r)) * 3072 + 2048 + h * 64 + dd];
    }
    __syncthreads();

    const int r0 = (tid >> 4) << 2;   // row block
    const int c0 = (tid & 15) << 2;   // col block (also used as d0 for y)

    // ---- scores = q @ k^T * scale (4x4 per thread) ----
    {
        float sc[4][4];
#pragma unroll
        for (int i = 0; i < 4; i++)
#pragma unroll
            for (int j = 0; j < 4; j++) sc[i][j] = 0.0f;
#pragma unroll 8
        for (int dd = 0; dd < 64; dd++) {
            float aq[4], bk[4];
#pragma unroll
            for (int i = 0; i < 4; i++) aq[i] = qs[(r0 + i) * 65 + dd];
#pragma unroll
            for (int j = 0; j < 4; j++) bk[j] = ks[(c0 + j) * 65 + dd];
#pragma unroll
            for (int i = 0; i < 4; i++)
#pragma unroll
                for (int j = 0; j < 4; j++)
                    sc[i][j] += aq[i] * bk[j];
        }
#pragma unroll
        for (int i = 0; i < 4; i++)
#pragma unroll
            for (int j = 0; j < 4; j++)
                ps[(r0 + i) * 65 + c0 + j] = sc[i][j] * 0.125f;
    }
    __syncthreads();

    // ---- softmax per row (64 rows handled by threads 0..63) ----
    if (tid < 64) {
        float* row = ps + tid * 65;
        float mx = -1e30f;
#pragma unroll 8
        for (int c = 0; c < 64; c++) mx = fmaxf(mx, row[c]);
        float sum = 0.0f;
#pragma unroll 8
        for (int c = 0; c < 64; c++) {
            float e = expf(row[c] - mx);
            row[c] = e;
            sum += e;
        }
        float inv = 1.0f / sum;
#pragma unroll 8
        for (int c = 0; c < 64; c++) row[c] *= inv;
    }
    __syncthreads();

    // ---- y = p @ v (4x4 per thread) ----
    {
        float acc[4][4];
#pragma unroll
        for (int i = 0; i < 4; i++)
#pragma unroll
            for (int j = 0; j < 4; j++) acc[i][j] = 0.0f;
#pragma unroll 8
        for (int c = 0; c < 64; c++) {
            float pv[4], vv[4];
#pragma unroll
            for (int i = 0; i < 4; i++) pv[i] = ps[(r0 + i) * 65 + c];
#pragma unroll
            for (int j = 0; j < 4; j++) vv[j] = vs[c * 65 + c0 + j];
#pragma unroll
            for (int i = 0; i < 4; i++)
#pragma unroll
                for (int j = 0; j < 4; j++)
                    acc[i][j] += pv[i] * vv[j];
        }
#pragma unroll
        for (int i = 0; i < 4; i++) {
            float4* yp = (float4*)(y + ((size_t)(b * T_ + n * 64 + r0 + i)) * 1024
                                     + h * 64 + c0);
            *yp = make_float4(acc[i][0], acc[i][1], acc[i][2], acc[i][3]);
        }
    }
}

// ---------------------------------------------------------------------------
extern "C" void kernel_launch(void* const* d_in, const int* in_sizes, int n_in,
                              void* d_out, int out_size)
{
    // Bind inputs BY ELEMENT COUNT, not by position — the three inputs have
    // pairwise-distinct sizes, so this is unambiguous and immune to any
    // metadata ordering mismatch:
    //   x      : 4*4096*1024      = 16,777,216
    //   w_attn : 3072*1024        =  3,145,728
    //   w_proj : 1024*1024        =  1,048,576
    const float* x      = nullptr;
    const float* w_attn = nullptr;
    const float* w_proj = nullptr;
    for (int i = 0; i < n_in; i++) {
        int sz = in_sizes[i];
        if      (sz == M_ * C_) x      = (const float*)d_in[i];
        else if (sz == F_ * C_) w_attn = (const float*)d_in[i];
        else if (sz == C_ * C_) w_proj = (const float*)d_in[i];
    }
    // Fallback to declared order if anything failed to match.
    if (!x)      x      = (const float*)d_in[0];
    if (!w_attn) w_attn = (const float*)d_in[1];
    if (!w_proj) w_proj = (const float*)d_in[2];

    float* out = (float*)d_out;

    float *qkv_ptr, *y_ptr;
    cudaGetSymbolAddress((void**)&qkv_ptr, g_qkv);
    cudaGetSymbolAddress((void**)&y_ptr, g_y);

    const int attn_smem = 4 * 64 * 65 * sizeof(float); // 66560 bytes
    cudaFuncSetAttribute(attn_kernel, cudaFuncAttributeMaxDynamicSharedMemorySize,
                         attn_smem);

    // qkv = x @ w_attn^T   (M=16384, N=3072, K=1024)
    gemm_tn<<<dim3(F_ / 128, M_ / 128), 256>>>(x, w_attn, qkv_ptr, M_, F_, C_);
    // chunked attention with RoPE
    attn_kernel<<<B_ * NC_ * H_, 256, attn_smem>>>(qkv_ptr, y_ptr);
    // out = y @ w_proj^T   (M=16384, N=1024, K=1024)
    gemm_tn<<<dim3(C_ / 128, M_ / 128), 256>>>(y_ptr, w_proj, out, M_, C_, C_);
}